// round 16
// baseline (speedup 1.0000x reference)
#include <cuda_runtime.h>
#include <cuda_fp16.h>
#include <cstdint>

#define KDIM 64
#define SDIM 512
#define TILE_M 128
#define NT 256
#define GRID 148
#define NTILES 512          // 65536 / 128
#define TAU 2.5e-3f
#define FLGMAX 512          // static stride -> max 4 tiles x 128 rows per CTA
#define INFF 3.4e38f

// smem byte offsets (144B pitch -> ldmatrix conflict-free; validated R6-R11)
#define OFF_BH   0          // 512 * 144
#define OFF_AH   73728      // 128 * 144
#define OFF_CN   92160      // 512 * 4
#define OFF_VN   94208      // 128 * 4
#define OFF_ZR   94720      // 128 * 4
#define OFF_RED  95232      // 128 * 4
#define OFF_FLG  95744      // FLGMAX * 4
#define OFF_CTL  97792      // fcnt
#define SMEM_TOTAL 97856

typedef unsigned long long ull;

__device__ float    g_tilesum[NTILES];
__device__ unsigned g_ticket;

__device__ __forceinline__ uint32_t smem_u32(const void* p) {
    uint32_t a;
    asm("{ .reg .u64 t; cvta.to.shared.u64 t, %1; cvt.u32.u64 %0, t; }" : "=r"(a) : "l"(p));
    return a;
}
__device__ __forceinline__ void ldsm4(uint32_t& r0, uint32_t& r1, uint32_t& r2, uint32_t& r3,
                                      uint32_t a) {
    asm volatile("ldmatrix.sync.aligned.m8n8.x4.shared.b16 {%0,%1,%2,%3}, [%4];"
                 : "=r"(r0), "=r"(r1), "=r"(r2), "=r"(r3) : "r"(a));
}
__device__ __forceinline__ void mma16816(float* d, const uint32_t* a,
                                         uint32_t b0, uint32_t b1) {
    asm volatile("mma.sync.aligned.m16n8k16.row.col.f32.f16.f16.f32 "
                 "{%0,%1,%2,%3}, {%4,%5,%6,%7}, {%8,%9}, {%0,%1,%2,%3};"
                 : "+f"(d[0]), "+f"(d[1]), "+f"(d[2]), "+f"(d[3])
                 : "r"(a[0]), "r"(a[1]), "r"(a[2]), "r"(a[3]), "r"(b0), "r"(b1));
}
struct R3 { float b, s; int i; };
__device__ __forceinline__ void mergeR(R3& a, const R3& o) {
    float ns = fminf(fminf(a.s, o.s), fmaxf(a.b, o.b));
    if (o.b < a.b) { a.b = o.b; a.i = o.i; }
    a.s = ns;
}
// branch-light best/second/idx update; strict < keeps earliest (lowest s) on ties
#define SCORE(v, sidx, lb, ls, li) do {            \
    float _v = (v);                                 \
    float _m = fmaxf(lb, _v);                       \
    ls = fminf(ls, _m);                             \
    bool _p = _v < lb;                              \
    lb = fminf(lb, _v);                             \
    li = _p ? (sidx) : li;                          \
} while (0)

// ---------------------------------------------------------------------------
// Single persistent kernel: 1-term fp16-hi HMMA screening (TAU margin flags)
// + inline exact cleanup + in-kernel loss reduction. 1 CTA/SM, 255-reg budget.
// Warp wid owns rows [wid*16, wid*16+16) x ALL 512 cols -> no cross-warp merge.
// ---------------------------------------------------------------------------
__global__ void __launch_bounds__(NT, 1)
vq_all(const float* __restrict__ vecs, const float* __restrict__ cb,
       float* __restrict__ out, int N, int ntiles, int nctas)
{
    extern __shared__ char smb[];
    float* cnsm   = (float*)(smb + OFF_CN);
    float* vn_s   = (float*)(smb + OFF_VN);
    int*   zrow   = (int*)(smb + OFF_ZR);
    float* redrow = (float*)(smb + OFF_RED);
    int*   flg    = (int*)(smb + OFF_FLG);
    int*   fcnt   = (int*)(smb + OFF_CTL);

    const int tid  = threadIdx.x;
    const int lane = tid & 31;
    const int wid  = tid >> 5;
    const int col2 = (lane & 3) * 2;

    if (tid == 0) fcnt[0] = 0;

    // ---- prologue: B hi-split -> smem (pitched 144B), cnorm -> smem ----
    for (int n = tid; n < SDIM * (KDIM / 4); n += NT) {
        int row = n >> 4, q = n & 15;
        float4 v = __ldg((const float4*)(cb + (long)row * KDIM) + q);
        __half2 h01 = __floats2half2_rn(v.x, v.y);
        __half2 h23 = __floats2half2_rn(v.z, v.w);
        uint2 hp; hp.x = *(uint32_t*)&h01; hp.y = *(uint32_t*)&h23;
        *(uint2*)(smb + OFF_BH + row * 144 + q * 8) = hp;
    }
    #pragma unroll
    for (int r = 0; r < SDIM / NT; r++) {
        int s = r * NT + tid;
        const float4* row = (const float4*)(cb + (long)s * KDIM);
        float a = 0.f;
        #pragma unroll
        for (int q = 0; q < KDIM / 4; q++) {
            float4 v = __ldg(row + q);
            a = fmaf(v.x, v.x, a);
            a = fmaf(v.y, v.y, a);
            a = fmaf(v.z, v.z, a);
            a = fmaf(v.w, v.w, a);
        }
        cnsm[s] = a;
    }

    // ldmatrix lane address components (layout validated R6-R11)
    const uint32_t a_lane_off =
        ((lane & 7) + ((lane >> 3) & 1) * 8) * 144 + (lane >> 4) * 16;
    const uint32_t b_lane_off =
        ((lane & 7) + ((lane >> 4) & 1) * 8) * 144 + ((lane >> 3) & 1) * 16;
    const uint32_t ah_base = smem_u32(smb + OFF_AH) + wid * 16 * 144 + a_lane_off;
    const uint32_t bh_base = smem_u32(smb + OFF_BH) + b_lane_off;

    // A-tile ownership: thread t handles row = t>>1, 32-float segment seg = t&1
    const int arow = tid >> 1;
    const int aseg = tid & 1;
    float* out_z = out + (long)N * KDIM;

    for (int tile = blockIdx.x; tile < ntiles; tile += nctas) {
        // ---- load + split A (LDG -> fp16 hi of -2*a -> smem; vn for loss) ----
        {
            const float4* src =
                (const float4*)(vecs + ((long)tile * TILE_M + arow) * KDIM) + aseg * 8;
            float p = 0.f;
            uint32_t hx[16];
            #pragma unroll
            for (int j = 0; j < 8; j++) {
                float4 v = __ldg(src + j);
                p = fmaf(v.x, v.x, p); p = fmaf(v.y, v.y, p);
                p = fmaf(v.z, v.z, p); p = fmaf(v.w, v.w, p);
                __half2 a = __floats2half2_rn(-2.f * v.x, -2.f * v.y);
                __half2 b = __floats2half2_rn(-2.f * v.z, -2.f * v.w);
                hx[j * 2] = *(uint32_t*)&a; hx[j * 2 + 1] = *(uint32_t*)&b;
            }
            char* dst = smb + OFF_AH + arow * 144 + aseg * 64;
            *(uint4*)(dst)      = *(uint4*)&hx[0];
            *(uint4*)(dst + 16) = *(uint4*)&hx[4];
            *(uint4*)(dst + 32) = *(uint4*)&hx[8];
            *(uint4*)(dst + 48) = *(uint4*)&hx[12];
            float po = __shfl_xor_sync(0xffffffffu, p, 1);
            if (aseg == 0) vn_s[arow] = p + po;   // loss-only (1e-3 tol)
        }
        __syncthreads();

        // ---- A fragments to registers once (16 regs, 4 ldsm) ----
        uint32_t af[4][4];
        #pragma unroll
        for (int kk = 0; kk < 4; kk++)
            ldsm4(af[kk][0], af[kk][1], af[kk][2], af[kk][3], ah_base + kk * 32);

        // ---- 8 subchunks of 64 cols: MMA + immediate scoring ----
        R3 runL = {INFF, INFF, 0}, runH = runL;

        #pragma unroll 1
        for (int sc = 0; sc < 8; sc++) {
            const int cbase = sc * 64;
            float acc[8][4];
            #pragma unroll
            for (int nb = 0; nb < 8; nb++)
                #pragma unroll
                for (int q = 0; q < 4; q++) acc[nb][q] = 0.f;

            #pragma unroll
            for (int kk = 0; kk < 4; kk++) {
                #pragma unroll
                for (int p = 0; p < 4; p++) {
                    uint32_t h0, h1, h2, h3;
                    ldsm4(h0, h1, h2, h3,
                          bh_base + (uint32_t)(cbase + p * 16) * 144 + kk * 32);
                    mma16816(acc[2 * p],     af[kk], h0, h1);
                    mma16816(acc[2 * p + 1], af[kk], h2, h3);
                }
            }

            float lbL = INFF, lsL = INFF, lbH = INFF, lsH = INFF;
            int liL = 0, liH = 0;
            #pragma unroll
            for (int nb = 0; nb < 8; nb++) {
                int c0 = cbase + nb * 8 + col2;
                float2 cn2 = *(const float2*)&cnsm[c0];
                SCORE(acc[nb][0] + cn2.x, c0,     lbL, lsL, liL);
                SCORE(acc[nb][1] + cn2.y, c0 + 1, lbL, lsL, liL);
                SCORE(acc[nb][2] + cn2.x, c0,     lbH, lsH, liH);
                SCORE(acc[nb][3] + cn2.y, c0 + 1, lbH, lsH, liH);
            }
            R3 cl = {lbL, lsL, liL}, chh = {lbH, lsH, liH};
            mergeR(runL, cl);
            mergeR(runH, chh);
        }

        // ---- quad reduce (lanes sharing the same row; cols ascend with lane) ----
        #pragma unroll
        for (int m = 1; m <= 2; m <<= 1) {
            R3 o;
            o.b = __shfl_xor_sync(0xffffffffu, runL.b, m);
            o.s = __shfl_xor_sync(0xffffffffu, runL.s, m);
            o.i = __shfl_xor_sync(0xffffffffu, runL.i, m);
            mergeR(runL, o);
            o.b = __shfl_xor_sync(0xffffffffu, runH.b, m);
            o.s = __shfl_xor_sync(0xffffffffu, runH.s, m);
            o.i = __shfl_xor_sync(0xffffffffu, runH.i, m);
            mergeR(runH, o);
        }

        // ---- warp owns its rows exclusively: write z/red/flags directly ----
        const long i0 = (long)tile * TILE_M;
        if ((lane & 3) == 0) {
            int row = wid * 16 + (lane >> 2);
            zrow[row] = runL.i;
            out_z[i0 + row] = (float)runL.i;
            redrow[row] = fmaxf(vn_s[row] + runL.b, 0.0f);
            if (runL.s - runL.b <= TAU) {
                int p = atomicAdd_block(fcnt, 1);
                if (p < FLGMAX) flg[p] = (int)(i0 + row);
            }
            row += 8;
            zrow[row] = runH.i;
            out_z[i0 + row] = (float)runH.i;
            redrow[row] = fmaxf(vn_s[row] + runH.b, 0.0f);
            if (runH.s - runH.b <= TAU) {
                int p = atomicAdd_block(fcnt, 1);
                if (p < FLGMAX) flg[p] = (int)(i0 + row);
            }
        }
        __syncthreads();

        // ---- gather vecs_hat = codebook[z]; per-tile loss sum ----
        for (int n = tid; n < TILE_M * (KDIM / 4); n += NT) {
            int row = n >> 4, q = n & 15;
            float4 v = __ldg((const float4*)(cb + (long)zrow[row] * KDIM) + q);
            *(float4*)(out + (i0 + row) * KDIM + q * 4) = v;
        }
        if (wid == 0) {
            float s = (redrow[lane] + redrow[lane + 32])
                    + (redrow[lane + 64] + redrow[lane + 96]);
            #pragma unroll
            for (int o = 16; o > 0; o >>= 1) s += __shfl_down_sync(0xffffffffu, s, o);
            if (lane == 0) g_tilesum[tile] = s;
        }
        __syncthreads();   // AH / vn_s free for next tile
    }

    // ---- inline exact cleanup (bit-identical reference rounding) ----
    {
        const int cnt = fcnt[0] < FLGMAX ? fcnt[0] : FLGMAX;
        for (int f = wid; f < cnt; f += NT / 32) {
            const int i = flg[f];
            const float* v = vecs + (long)i * KDIM;
            float vn = 0.f;
            #pragma unroll
            for (int q = 0; q < KDIM / 4; q++) {
                float4 t = __ldg((const float4*)v + q);
                vn = fmaf(t.x, t.x, vn);
                vn = fmaf(t.y, t.y, vn);
                vn = fmaf(t.z, t.z, vn);
                vn = fmaf(t.w, t.w, vn);
            }
            ull bk = ~0ull;
            for (int jj = 0; jj < 16; jj++) {
                int s = lane * 16 + jj;
                const float* c = cb + (long)s * KDIM;
                float ae = 0.f, ao = 0.f;   // even/odd fma chains (R2+ exactness)
                #pragma unroll
                for (int kp = 0; kp < KDIM / 2; kp++) {
                    ae = fmaf(v[2 * kp],     c[2 * kp],     ae);
                    ao = fmaf(v[2 * kp + 1], c[2 * kp + 1], ao);
                }
                float dot = __fadd_rn(ae, ao);
                float d = __fadd_rn(__fmaf_rn(-2.0f, dot, vn), cnsm[s]);
                ull key = ((ull)__float_as_uint(d) << 32) | (unsigned)s;
                bk = key < bk ? key : bk;
            }
            #pragma unroll
            for (int o = 16; o > 0; o >>= 1) {
                ull other = __shfl_xor_sync(0xffffffffu, bk, o);
                bk = other < bk ? other : bk;
            }
            int z = (int)(bk & 0xffffffffull);
            if (lane == 0) out_z[i] = (float)z;
            out[(long)i * KDIM + lane]      = __ldg(&cb[(long)z * KDIM + lane]);
            out[(long)i * KDIM + lane + 32] = __ldg(&cb[(long)z * KDIM + lane + 32]);
        }
    }

    // ---- last CTA: fixed-order loss reduction ----
    __syncthreads();
    if (tid < 32) {
        unsigned t = 0xffffffffu;
        if (tid == 0) { __threadfence(); t = atomicAdd(&g_ticket, 1u); }
        t = __shfl_sync(0xffffffffu, t, 0);
        if (t == (unsigned)(nctas - 1)) {
            __threadfence();
            double s = 0.0;
            for (int j = 0; j < NTILES / 32; j++)
                s += (double)__ldcg(&g_tilesum[lane * (NTILES / 32) + j]);
            #pragma unroll
            for (int o = 16; o > 0; o >>= 1) s += __shfl_down_sync(0xffffffffu, s, o);
            if (lane == 0) {
                float mean = (float)(s / (double)N);
                long base = (long)N * KDIM + N;
                out[base]     = mean;   // l_commit
                out[base + 1] = mean;   // l_codebook (identical forward value)
                g_ticket = 0;
            }
        }
    }
}

extern "C" void kernel_launch(void* const* d_in, const int* in_sizes, int n_in,
                              void* d_out, int out_size) {
    const float* vecs = (const float*)d_in[0];
    const float* cb   = (const float*)d_in[1];
    float* out = (float*)d_out;

    int N = in_sizes[0] / KDIM;          // 65536
    int ntiles = N / TILE_M;             // 512

    cudaFuncSetAttribute(vq_all, cudaFuncAttributeMaxDynamicSharedMemorySize, SMEM_TOTAL);
    vq_all<<<GRID, NT, SMEM_TOTAL>>>(vecs, cb, out, N, ntiles, GRID);
}

// round 17
// speedup vs baseline: 2.7878x; 2.7878x over previous
#include <cuda_runtime.h>
#include <cstdint>

#define KDIM 64
#define TILE 32             // vectors per tile
#define NT 128              // 4 warps per CTA
#define NPAIRS 148
#define GRID (2 * NPAIRS)   // 296 CTAs = exactly 2 per SM (one wave)
#define NTILES 2048         // 65536 / 32
#define PITCH 68            // floats/row; float4 lane-stride 17 (mod 8) conflict-free
#define HALF_S 256          // codewords per CTA (codebook half)

// smem layout (floats): cbs[256*68] | stage[2*32*68] | cns[256] | vns[32] | kbuf
#define F_CBS   0
#define F_STG   (HALF_S * PITCH)                  // 17408
#define F_CNS   (F_STG + 2 * TILE * PITCH)        // +4352
#define F_VNS   (F_CNS + HALF_S)
#define F_KB    (F_VNS + TILE)                    // ull-aligned (all offsets /2 even)
#define SMEM_FLOATS (F_KB + TILE * 4 * 2)
#define SMEM_BYTES (SMEM_FLOATS * 4)

typedef unsigned long long ull;

__device__ ull      g_key[65536 * 2];   // [v][half]; fully overwritten each replay
__device__ float    g_psum[GRID];
__device__ unsigned g_bar1;             // zero-init; reset by last CTA each replay
__device__ unsigned g_bar2;

__device__ __forceinline__ void ffma2(ull& d, ull a, ull b) {
    asm volatile("fma.rn.f32x2 %0, %1, %2, %0;" : "+l"(d) : "l"(a), "l"(b));
}
__device__ __forceinline__ void cp16(void* dst, const void* src) {
    unsigned d;
    asm("{ .reg .u64 t; cvta.to.shared.u64 t, %1; cvt.u32.u64 %0, t; }" : "=r"(d) : "l"(dst));
    asm volatile("cp.async.cg.shared.global [%0], [%1], 16;" :: "r"(d), "l"(src));
}
__device__ __forceinline__ void cp_commit() { asm volatile("cp.async.commit_group;"); }

// monotone float<->uint encoding (total order matching float <), validated R12-R15
__device__ __forceinline__ unsigned fenc(float f) {
    unsigned b = __float_as_uint(f);
    return b ^ ((unsigned)((int)b >> 31) | 0x80000000u);
}
__device__ __forceinline__ float fdec(unsigned e) {
    unsigned b = e ^ ((unsigned)((int)(~e) >> 31) | 0x80000000u);
    return __uint_as_float(b);
}

// ---------------------------------------------------------------------------
// Phase 1: CTA pair (2p, 2p+1) scans the same vector tiles against
// complementary 256-codeword halves (independent barriers -> LDS/FMA overlap).
// Phase 2 (after in-kernel grid barrier): merge halves, z, gather, losses.
// Exact reference rounding everywhere (bit-identical to R13).
// ---------------------------------------------------------------------------
__global__ void __launch_bounds__(NT, 2)
vq_main(const float* __restrict__ vecs, const float* __restrict__ cb,
        float* __restrict__ out, int N)
{
    extern __shared__ float sm[];
    float* cbs = sm + F_CBS;
    float* stg = sm + F_STG;
    float* cns = sm + F_CNS;
    float* vns = sm + F_VNS;
    ull*   kbuf = (ull*)(sm + F_KB);     // [v][warp] : 32 x 4

    const int tid  = threadIdx.x;
    const int lane = tid & 31;
    const int wid  = tid >> 5;           // 0..3
    const int lv   = lane >> 3;          // vector sub-row 0..3
    const int lc   = lane & 7;           // codeword sub-col 0..7
    const int pair = blockIdx.x >> 1;
    const int half = blockIdx.x & 1;
    const int sbase = half * HALF_S;     // global codeword base of this CTA

    float* out_z = out + (long)N * KDIM;

    // ---- prologue: codebook half -> pitched smem, first A tile, cnorms ----
    for (int n = tid; n < HALF_S * 16; n += NT) {
        int row = n >> 4, q = n & 15;
        cp16(cbs + row * PITCH + q * 4, cb + (long)(sbase + row) * KDIM + q * 4);
    }
    {
        const float* src = vecs + (long)pair * TILE * KDIM;
        for (int n = tid; n < TILE * 16; n += NT) {
            int row = n >> 4, q = n & 15;
            cp16(stg + row * PITCH + q * 4, src + row * KDIM + q * 4);
        }
    }
    cp_commit();

    #pragma unroll
    for (int r = 0; r < HALF_S / NT; r++) {
        int s = r * NT + tid;
        const float4* row = (const float4*)(cb + (long)(sbase + s) * KDIM);
        float a = 0.f;
        #pragma unroll
        for (int q = 0; q < 16; q++) {
            float4 v = __ldg(row + q);
            a = fmaf(v.x, v.x, a);
            a = fmaf(v.y, v.y, a);
            a = fmaf(v.z, v.z, a);
            a = fmaf(v.w, v.w, a);
        }
        cns[s] = a;
    }
    __syncthreads();

    float cnr[8];
    #pragma unroll
    for (int jj = 0; jj < 8; jj++) cnr[jj] = cns[wid * 64 + lc + 8 * jj];
    const float* bb = cbs + (wid * 64 + lc) * PITCH;

    int buf = 0;
    for (int tile = pair; tile < NTILES; tile += NPAIRS) {
        asm volatile("cp.async.wait_group 0;");
        __syncthreads();

        const float* st = stg + buf * (TILE * PITCH);

        // per-vector norms (exact float4 chain)
        if (tid < TILE) {
            const float* vr = st + tid * PITCH;
            float a = 0.f;
            #pragma unroll
            for (int q = 0; q < 16; q++) {
                float4 v = *(const float4*)(vr + q * 4);
                a = fmaf(v.x, v.x, a);
                a = fmaf(v.y, v.y, a);
                a = fmaf(v.z, v.z, a);
                a = fmaf(v.w, v.w, a);
            }
            vns[tid] = a;
        }
        // prefetch next A tile into the other buffer
        if (tile + NPAIRS < NTILES) {
            const float* src = vecs + (long)(tile + NPAIRS) * TILE * KDIM;
            float* dst = stg + (buf ^ 1) * (TILE * PITCH);
            for (int n = tid; n < TILE * 16; n += NT) {
                int row = n >> 4, q = n & 15;
                cp16(dst + row * PITCH + q * 4, src + row * KDIM + q * 4);
            }
        }
        cp_commit();
        __syncthreads();

        // ---- mainloop: 16 ksteps, 8x8 ull accumulators (R13 verbatim) ----
        ull acc[8][8];
        #pragma unroll
        for (int ii = 0; ii < 8; ii++)
            #pragma unroll
            for (int jj = 0; jj < 8; jj++) acc[ii][jj] = 0ull;

        const float* ab = st + lv * PITCH;

        #pragma unroll 1
        for (int kc = 0; kc < 16; ++kc) {
            ulonglong2 af[8], bf[8];
            #pragma unroll
            for (int ii = 0; ii < 8; ii++)
                af[ii] = *(const ulonglong2*)(ab + ii * 4 * PITCH + kc * 4);
            #pragma unroll
            for (int jj = 0; jj < 8; jj++)
                bf[jj] = *(const ulonglong2*)(bb + jj * 8 * PITCH + kc * 4);
            #pragma unroll
            for (int ii = 0; ii < 8; ii++)
                #pragma unroll
                for (int jj = 0; jj < 8; jj++) {
                    ffma2(acc[ii][jj], af[ii].x, bf[jj].x);
                    ffma2(acc[ii][jj], af[ii].y, bf[jj].y);
                }
        }

        // ---- epilogue: exact scores, per-vector argmin (lowest global s) ----
        #pragma unroll
        for (int ii = 0; ii < 8; ii++) {
            const int v = 4 * ii + lv;
            const float vn = vns[v];
            ull bk = ~0ull;
            #pragma unroll
            for (int jj = 0; jj < 8; jj++) {
                float lo = __uint_as_float((unsigned)(acc[ii][jj] & 0xffffffffull));
                float hi = __uint_as_float((unsigned)(acc[ii][jj] >> 32));
                float dot = __fadd_rn(lo, hi);
                float d = __fadd_rn(__fmaf_rn(-2.0f, dot, vn), cnr[jj]);
                int s = sbase + wid * 64 + lc + 8 * jj;
                ull key = ((ull)fenc(d) << 32) | (unsigned)s;
                bk = key < bk ? key : bk;
            }
            #pragma unroll
            for (int m = 1; m <= 4; m <<= 1) {
                ull o = __shfl_xor_sync(0xffffffffu, bk, m);
                bk = o < bk ? o : bk;
            }
            if (lc == 0) kbuf[v * 4 + wid] = bk;
        }
        __syncthreads();

        // cross-warp merge -> g_key (plain store, partitioned by (v, half))
        if (tid < TILE) {
            ull bk = kbuf[tid * 4];
            #pragma unroll
            for (int w = 1; w < 4; w++) {
                ull k = kbuf[tid * 4 + w];
                bk = k < bk ? k : bk;
            }
            g_key[((long)tile * TILE + tid) * 2 + half] = bk;
        }
        buf ^= 1;
        __syncthreads();
    }

    // ---- grid barrier (all 296 CTAs resident -> safe) ----
    __syncthreads();
    if (tid == 0) {
        __threadfence();
        atomicAdd(&g_bar1, 1u);
        volatile unsigned* p = &g_bar1;
        while (*p < (unsigned)GRID) __nanosleep(256);
        __threadfence();
    }
    __syncthreads();

    // ---- phase 2: merge halves, z, err, coalesced gather ----
    {
        const int gw = (blockIdx.x * NT + tid) >> 5;   // global warp 0..1183
        const int ngw = (GRID * NT) >> 5;
        float esum = 0.f;
        for (int g = gw; g < NTILES; g += ngw) {
            long v = (long)g * 32 + lane;
            ulonglong2 kk = *(const ulonglong2*)&g_key[v * 2];
            ull bk = kk.x < kk.y ? kk.x : kk.y;
            int z = (int)(bk & 0xffffffffull);
            float d = fdec((unsigned)(bk >> 32));
            out_z[v] = (float)z;
            esum += fmaxf(d, 0.0f);
            // gather codebook[z] for all 32 vectors, coalesced (lane = float2 idx)
            #pragma unroll 4
            for (int j = 0; j < 32; j++) {
                int zj = __shfl_sync(0xffffffffu, z, j);
                long vj = (long)g * 32 + j;
                float2 c = __ldg((const float2*)(cb + (long)zj * KDIM) + lane);
                *(float2*)(out + vj * KDIM + lane * 2) = c;
            }
        }
        // per-CTA deterministic loss partial
        #pragma unroll
        for (int o = 16; o > 0; o >>= 1) esum += __shfl_down_sync(0xffffffffu, esum, o);
        __syncthreads();                 // reuse kbuf smem for warp partials
        if (lane == 0) ((float*)kbuf)[wid] = esum;
        __syncthreads();
        if (tid == 0) {
            float s = (((float*)kbuf)[0] + ((float*)kbuf)[1])
                    + (((float*)kbuf)[2] + ((float*)kbuf)[3]);
            g_psum[blockIdx.x] = s;
            __threadfence();
            unsigned t = atomicAdd(&g_bar2, 1u);
            if (t == (unsigned)(GRID - 1)) {
                double tot = 0.0;
                for (int i = 0; i < GRID; i++)
                    tot += (double)(*(volatile float*)&g_psum[i]);
                float mean = (float)(tot / (double)N);
                long base = (long)N * KDIM + N;
                out[base]     = mean;   // l_commit
                out[base + 1] = mean;   // l_codebook (identical forward value)
                g_bar1 = 0;             // reset for next graph replay
                g_bar2 = 0;
            }
        }
    }
}

extern "C" void kernel_launch(void* const* d_in, const int* in_sizes, int n_in,
                              void* d_out, int out_size) {
    const float* vecs = (const float*)d_in[0];
    const float* cb   = (const float*)d_in[1];
    float* out = (float*)d_out;

    int N = in_sizes[0] / KDIM;          // 65536

    cudaFuncSetAttribute(vq_main, cudaFuncAttributeMaxDynamicSharedMemorySize,
                         SMEM_BYTES);
    vq_main<<<GRID, NT, SMEM_BYTES>>>(vecs, cb, out, N);
}